// round 1
// baseline (speedup 1.0000x reference)
#include <cuda_runtime.h>
#include <cstdint>

#define N_TOK   131072
#define N_E     1024
#define E_DIM   256

#define TM      128      // tokens per block
#define TN      64       // codes per inner tile
#define NTILES  (N_E / TN)
#define PAD_K   260      // padded row stride (floats) -> 2-phase LDS, no heavy conflicts
#define THREADS 512

__device__ float        d_wnorm[N_E];
__device__ unsigned int d_counts[N_E];

// ---------------------------------------------------------------------------
// Kernel 0: per-code squared norms + zero the count buffer (re-run safe for
// graph replay: every replay re-zeroes counts before the main kernel).
// grid = 128 blocks x 256 threads, one warp per code row.
// ---------------------------------------------------------------------------
__global__ void vq_prep_kernel(const float* __restrict__ w) {
    int warp = (blockIdx.x * blockDim.x + threadIdx.x) >> 5;
    int lane = threadIdx.x & 31;
    if (warp < N_E) {
        const float4* row = reinterpret_cast<const float4*>(w + (size_t)warp * E_DIM);
        float s = 0.0f;
        #pragma unroll
        for (int i = 0; i < 2; i++) {
            float4 v = row[lane + 32 * i];
            s = fmaf(v.x, v.x, s);
            s = fmaf(v.y, v.y, s);
            s = fmaf(v.z, v.z, s);
            s = fmaf(v.w, v.w, s);
        }
        #pragma unroll
        for (int off = 16; off; off >>= 1)
            s += __shfl_xor_sync(0xffffffffu, s, off);
        if (lane == 0) {
            d_wnorm[warp]  = s;
            d_counts[warp] = 0u;
        }
    }
}

// ---------------------------------------------------------------------------
// Kernel 1: fused  scores -> argmin -> z_q gather -> code counts.
// Each block owns TM=128 tokens, keeps their full K=256 rows in SMEM, and
// streams the 1024-code codebook through SMEM in 16 tiles of 64, maintaining
// a running (min-dist, idx) per token. dist = ||w||^2 - 2*z.w  (||z||^2 is a
// per-token constant, irrelevant to argmin).
// Thread grid 16(tx: codes) x 32(ty: tokens); micro-tile 4x4, strided
// assignment (code n = tx + 16j, token m = ty + 32i) for conflict-light LDS.
// ---------------------------------------------------------------------------
__global__ __launch_bounds__(THREADS, 1)
void vq_main_kernel(const float* __restrict__ z,
                    const float* __restrict__ w,
                    float* __restrict__ out) {
    extern __shared__ float sm[];
    float* zs   = sm;                                // [TM][PAD_K]
    float* ws   = zs + TM * PAD_K;                   // [TN][PAD_K]
    float* wn   = ws + TN * PAD_K;                   // [N_E]
    int*   sidx = reinterpret_cast<int*>(wn + N_E);  // [TM]

    const int tid = threadIdx.x;
    const int t0  = blockIdx.x * TM;

    // stage all 1024 code norms once
    for (int i = tid; i < N_E; i += THREADS) wn[i] = d_wnorm[i];

    // stage z tile [TM][E_DIM] row-major (coalesced float4, conflict-free STS)
    {
        const int kk    = (tid & 63) * 4;
        const int mbase = tid >> 6;          // 0..7
        #pragma unroll
        for (int it = 0; it < 16; it++) {
            int m = mbase + it * 8;
            float4 v = *reinterpret_cast<const float4*>(
                z + (size_t)(t0 + m) * E_DIM + kk);
            *reinterpret_cast<float4*>(zs + m * PAD_K + kk) = v;
        }
    }

    const int tx = tid & 15;    // code lane
    const int ty = tid >> 4;    // token lane (0..31)

    float bestv[4];
    int   besti[4];
    #pragma unroll
    for (int i = 0; i < 4; i++) { bestv[i] = 3.4e38f; besti[i] = 0x7fffffff; }

    for (int tile = 0; tile < NTILES; tile++) {
        const int c0 = tile * TN;

        __syncthreads();   // previous tile's ws fully consumed
        // stage w tile [TN][E_DIM]
        {
            const int kk    = (tid & 63) * 4;
            const int nbase = tid >> 6;
            #pragma unroll
            for (int it = 0; it < 8; it++) {
                int n = nbase + it * 8;
                float4 v = *reinterpret_cast<const float4*>(
                    w + (size_t)(c0 + n) * E_DIM + kk);
                *reinterpret_cast<float4*>(ws + n * PAD_K + kk) = v;
            }
        }
        __syncthreads();

        float acc[4][4];
        #pragma unroll
        for (int i = 0; i < 4; i++)
            #pragma unroll
            for (int j = 0; j < 4; j++) acc[i][j] = 0.0f;

        #pragma unroll 4
        for (int k = 0; k < E_DIM; k += 4) {
            float4 a[4], b[4];
            #pragma unroll
            for (int i = 0; i < 4; i++)
                a[i] = *reinterpret_cast<const float4*>(zs + (ty + 32 * i) * PAD_K + k);
            #pragma unroll
            for (int j = 0; j < 4; j++)
                b[j] = *reinterpret_cast<const float4*>(ws + (tx + 16 * j) * PAD_K + k);
            #pragma unroll
            for (int i = 0; i < 4; i++) {
                #pragma unroll
                for (int j = 0; j < 4; j++) {
                    acc[i][j] = fmaf(a[i].x, b[j].x, acc[i][j]);
                    acc[i][j] = fmaf(a[i].y, b[j].y, acc[i][j]);
                    acc[i][j] = fmaf(a[i].z, b[j].z, acc[i][j]);
                    acc[i][j] = fmaf(a[i].w, b[j].w, acc[i][j]);
                }
            }
        }

        // fold tile into running argmin (tie -> lower index, like jnp.argmin)
        #pragma unroll
        for (int j = 0; j < 4; j++) {
            int   n   = c0 + tx + 16 * j;
            float wnv = wn[n];
            #pragma unroll
            for (int i = 0; i < 4; i++) {
                float dist = fmaf(-2.0f, acc[i][j], wnv);
                if (dist < bestv[i] || (dist == bestv[i] && n < besti[i])) {
                    bestv[i] = dist;
                    besti[i] = n;
                }
            }
        }
    }

    // reduce argmin across the 16 code-lanes (stays inside a half-warp)
    #pragma unroll
    for (int off = 1; off < 16; off <<= 1) {
        #pragma unroll
        for (int i = 0; i < 4; i++) {
            float ov = __shfl_xor_sync(0xffffffffu, bestv[i], off);
            int   oi = __shfl_xor_sync(0xffffffffu, besti[i], off);
            if (ov < bestv[i] || (ov == bestv[i] && oi < besti[i])) {
                bestv[i] = ov;
                besti[i] = oi;
            }
        }
    }

    if (tx == 0) {
        #pragma unroll
        for (int i = 0; i < 4; i++) {
            int m = ty + 32 * i;
            sidx[m] = besti[i];
            atomicAdd(&d_counts[besti[i]], 1u);
        }
    }
    __syncthreads();

    // fused gather epilogue: out = z + (w[idx] - z), z comes from SMEM
    {
        const int kk    = (tid & 63) * 4;
        const int mbase = tid >> 6;
        #pragma unroll
        for (int it = 0; it < 16; it++) {
            int m  = mbase + it * 8;
            int ci = sidx[m];
            float4 wv = *reinterpret_cast<const float4*>(
                w + (size_t)ci * E_DIM + kk);
            const float* zp = zs + m * PAD_K + kk;
            float4 o;
            o.x = zp[0] + (wv.x - zp[0]);
            o.y = zp[1] + (wv.y - zp[1]);
            o.z = zp[2] + (wv.z - zp[2]);
            o.w = zp[3] + (wv.w - zp[3]);
            *reinterpret_cast<float4*>(out + (size_t)(t0 + m) * E_DIM + kk) = o;
        }
    }
}

// ---------------------------------------------------------------------------
// Kernel 2: perplexity = exp(-sum(e_mean * log(e_mean + 1e-10)))
// ---------------------------------------------------------------------------
__global__ void vq_perplexity_kernel(float* __restrict__ out_perp) {
    __shared__ float red[N_E];
    int t = threadIdx.x;
    float e    = (float)d_counts[t] * (1.0f / (float)N_TOK);
    red[t]     = -e * logf(e + 1e-10f);
    __syncthreads();
    #pragma unroll
    for (int s = N_E / 2; s > 0; s >>= 1) {
        if (t < s) red[t] += red[t + s];
        __syncthreads();
    }
    if (t == 0) *out_perp = expf(red[0]);
}

// ---------------------------------------------------------------------------
extern "C" void kernel_launch(void* const* d_in, const int* in_sizes, int n_in,
                              void* d_out, int out_size) {
    const float* z = (const float*)d_in[0];   // [N_TOK, E_DIM]
    const float* w = (const float*)d_in[1];   // [N_E, E_DIM]
    float* out = (float*)d_out;

    size_t smem_bytes = (size_t)(TM * PAD_K + TN * PAD_K + N_E) * sizeof(float)
                        + (size_t)TM * sizeof(int);
    cudaFuncSetAttribute(vq_main_kernel,
                         cudaFuncAttributeMaxDynamicSharedMemorySize,
                         (int)smem_bytes);

    vq_prep_kernel<<<128, 256>>>(w);
    vq_main_kernel<<<N_TOK / TM, THREADS, smem_bytes>>>(z, w, out);

    // output layout: z_q [N_TOK*E_DIM] followed by scalar perplexity
    if (out_size > N_TOK * E_DIM) {
        vq_perplexity_kernel<<<1, N_E>>>(out + (size_t)N_TOK * E_DIM);
    }
}